// round 15
// baseline (speedup 1.0000x reference)
#include <cuda_runtime.h>
#include <cuda_bf16.h>
#include <cuda_fp16.h>
#include <cstdint>
#include <math.h>

#define HID 128
#define MAXN 50000
#define MAXE 800000

typedef unsigned long long ull;

// ---------------- scratch (device globals; zero-initialized at load) ----------------
__device__ int   g_counts[MAXN + 1];   // scan_kernel re-zeroes after use each call
__device__ int   g_off[MAXN + 1];
__device__ int   g_cursor[MAXN];
__device__ int   g_esrc[MAXE];
__device__ ull   g_x16[(size_t)MAXN * 32];    // x as fp16 rows (128 halves = 32 ull)
__device__ ull   g_h16[(size_t)MAXN * 32];    // h1 as fp16 rows
__device__ ull   g_aggr16[(size_t)MAXN * 32]; // mean-aggregated features, fp16
__device__ float g_h2[(size_t)MAXN * HID];    // fallback h buffer (fp32)
// W fp16, pre-laid-out as [col][264 halves] (word stride 132), per layer
__device__ uint4 g_whi[2][4224];   // 2 x 67584 B

#define MMA_F16(c, a0, a1, a2, a3, b0, b1) \
    asm volatile("mma.sync.aligned.m16n8k16.row.col.f32.f16.f16.f32 " \
        "{%0,%1,%2,%3}, {%4,%5,%6,%7}, {%8,%9}, {%0,%1,%2,%3};" \
        : "+f"((c)[0]), "+f"((c)[1]), "+f"((c)[2]), "+f"((c)[3]) \
        : "r"(a0), "r"(a1), "r"(a2), "r"(a3), "r"(b0), "r"(b1))

#define LDSM_X4(r0, r1, r2, r3, addr) \
    asm volatile("ldmatrix.sync.aligned.m8n8.x4.shared.b16 {%0,%1,%2,%3}, [%4];" \
        : "=r"(r0), "=r"(r1), "=r"(r2), "=r"(r3) : "r"(addr))

__device__ __forceinline__ uint32_t smem_u32(const void* p) {
    uint32_t a;
    asm("{ .reg .u64 t; cvta.to.shared.u64 t, %1; cvt.u32.u64 %0, t; }" : "=r"(a) : "l"(p));
    return a;
}

// ---------------- launch 1: edge histogram + x->fp16 convert (fused, independent) ----------------
__global__ void hist_xcvt_kernel(const int* __restrict__ dst, int* __restrict__ counts, int E,
                                 const float* __restrict__ x, ull* __restrict__ x16, int total4) {
    int i = blockIdx.x * blockDim.x + threadIdx.x;
    if (i < E) atomicAdd(&counts[dst[i]], 1);
    if (i < total4) {
        float4 v = ((const float4*)x)[i];
        __half2 h0 = __float22half2_rn(make_float2(v.x, v.y));
        __half2 h1 = __float22half2_rn(make_float2(v.z, v.w));
        x16[i] = (ull)(*(uint32_t*)&h0) | ((ull)(*(uint32_t*)&h1) << 32);
    }
}

// ---------------- launch 2: single-block scan ----------------
__global__ void scan_kernel(int* __restrict__ counts, int* __restrict__ off,
                            int* __restrict__ cursor, int n) {
    __shared__ int part[1024];
    int tid = threadIdx.x;
    int chunk = (n + 1023) >> 10;
    int start = tid * chunk;
    int end = start + chunk; if (end > n) end = n;
    int s = 0;
    #pragma unroll 4
    for (int i = start; i < end; i++) s += counts[i];
    part[tid] = s;
    __syncthreads();
    for (int d = 1; d < 1024; d <<= 1) {
        int v = (tid >= d) ? part[tid - d] : 0;
        __syncthreads();
        part[tid] += v;
        __syncthreads();
    }
    int pre = (tid == 0) ? 0 : part[tid - 1];
    for (int i = start; i < end; i++) {
        int c = counts[i];
        counts[i] = 0;          // leave zeroed for next call's hist
        off[i] = pre;
        cursor[i] = pre;
        pre += c;
    }
    if (end == n) off[n] = pre;
}

// ---------------- launch 3: CSR fill ----------------
__global__ void fill_kernel(const int* __restrict__ src, const int* __restrict__ dst,
                            int* __restrict__ cursor, int* __restrict__ esrc, int E) {
    int e = blockIdx.x * blockDim.x + threadIdx.x;
    if (e < E) {
        int d = dst[e];
        int pos = atomicAdd(&cursor[d], 1);
        esrc[pos] = src[e];
    }
}

// ---------------- launch 4: W fp16 convert ----------------
__global__ void wsplit_kernel(const float* __restrict__ W1l, const float* __restrict__ W1r,
                              const float* __restrict__ W2l, const float* __restrict__ W2r) {
    int idx = blockIdx.x * blockDim.x + threadIdx.x;   // 2*256*128 = 65536
    if (idx >= 2 * 256 * 128) return;
    int layer = idx >> 15;
    int r = idx & 32767;
    int k = r >> 7;
    int col = r & 127;
    const float* srcm;
    if (layer == 0) srcm = (k < 128) ? (W1l + (size_t)k * 128) : (W1r + (size_t)(k - 128) * 128);
    else            srcm = (k < 128) ? (W2l + (size_t)k * 128) : (W2r + (size_t)(k - 128) * 128);
    float w = srcm[col];
    __half h = __float2half(w);
    ((uint16_t*)g_whi[layer])[col * 264 + k] = *(uint16_t*)&h;
}

// ---------------- gather-aggregate (mean) over fp16 rows: warp per dst node, MLP=8 ----------------
__global__ void gather_kernel(const ull* __restrict__ feat16, const int* __restrict__ esrc,
                              const int* __restrict__ off, ull* __restrict__ aggr16, int n) {
    int w = (blockIdx.x * blockDim.x + threadIdx.x) >> 5;
    int lane = threadIdx.x & 31;
    if (w >= n) return;
    int o0 = off[w], o1 = off[w + 1];
    float a0 = 0.f, a1 = 0.f, a2 = 0.f, a3 = 0.f;
    int k = o0;
    for (; k + 8 <= o1; k += 8) {
        ull vv[8];
        #pragma unroll
        for (int e = 0; e < 8; e++) {
            int s = __ldg(esrc + k + e);
            vv[e] = feat16[(size_t)s * 32 + lane];
        }
        #pragma unroll
        for (int e = 0; e < 8; e++) {
            uint32_t lo = (uint32_t)vv[e], hi = (uint32_t)(vv[e] >> 32);
            float2 f0 = __half22float2(*(__half2*)&lo);
            float2 f1 = __half22float2(*(__half2*)&hi);
            a0 += f0.x; a1 += f0.y; a2 += f1.x; a3 += f1.y;
        }
    }
    for (; k < o1; k++) {
        int s = __ldg(esrc + k);
        ull v = feat16[(size_t)s * 32 + lane];
        uint32_t lo = (uint32_t)v, hi = (uint32_t)(v >> 32);
        float2 f0 = __half22float2(*(__half2*)&lo);
        float2 f1 = __half22float2(*(__half2*)&hi);
        a0 += f0.x; a1 += f0.y; a2 += f1.x; a3 += f1.y;
    }
    float inv = 1.0f / fmaxf((float)(o1 - o0), 1.0f);
    __half2 r0 = __float22half2_rn(make_float2(a0 * inv, a1 * inv));
    __half2 r1 = __float22half2_rn(make_float2(a2 * inv, a3 * inv));
    aggr16[(size_t)w * 32 + lane] = (ull)(*(uint32_t*)&r0) | ((ull)(*(uint32_t*)&r1) << 32);
}

// ---------------- HMMA (mma.sync fp16 + ldmatrix) SAGE layer, 2 CTAs/SM ----------------
// out[i][j] = relu( b[j] + sum_{k<256} S[i][k] W[k][j] ), S=[A|X] (fp16), W=[Wl;Wr] (fp16).
// A-fragments loaded via ldmatrix.x4 (1 instr per m-tile per kstep instead of 4 LDS.32).
#define WSTRIDE 132
#define SSTRIDE 68
#define SM_BIAS 0
#define SM_WHI  512
#define SM_S    (512 + 128 * WSTRIDE * 4)
#define LAYER_SMEM (SM_S + 128 * SSTRIDE * 4)

__global__ void __launch_bounds__(256, 2)
layer_kernel(const ull* __restrict__ A16, const ull* __restrict__ X16,
             const uint4* __restrict__ whi, const float* __restrict__ bias,
             float* __restrict__ outF32, ull* __restrict__ outF16,
             int n, int outIsF16) {
    extern __shared__ char smem[];
    float* sBias = (float*)(smem + SM_BIAS);
    uint32_t* sWhi = (uint32_t*)(smem + SM_WHI);
    uint32_t* sS   = (uint32_t*)(smem + SM_S);

    int tid = threadIdx.x;
    int wid = tid >> 5;
    int lane = tid & 31;
    int g = lane >> 2;
    int t = lane & 3;
    int n0 = wid * 16;

    // ldmatrix per-lane source row/col within the S tile
    int rowA = (lane & 7) + ((lane >> 3) & 1) * 8;   // 0..15
    int colsel = (lane >> 4) * 4;                    // 0 or 4 words
    uint32_t sSu = smem_u32(smem + SM_S);
    uint32_t aBase = sSu + (uint32_t)((rowA * SSTRIDE + colsel) * 4);

    // ---- stage W: pure linear copy (4224 uint4) ----
    {
        uint4* dh = (uint4*)sWhi;
        for (int i = tid; i < 4224; i += 256) dh[i] = whi[i];
        if (tid < 128) sBias[tid] = bias[tid];
    }

    int nTiles = (n + 127) >> 7;
    for (int tile = blockIdx.x; tile < nTiles; tile += gridDim.x) {
        float acc[8][2][4];
        #pragma unroll
        for (int m = 0; m < 8; m++)
            #pragma unroll
            for (int nt = 0; nt < 2; nt++)
                #pragma unroll
                for (int q = 0; q < 4; q++) acc[m][nt][q] = 0.f;

        #pragma unroll
        for (int kc = 0; kc < 2; kc++) {
            __syncthreads();   // protects sS reuse (and sW staging on first pass)
            // stage S chunk (128 nodes x 128 k): pure 8B copy, warp = 1 node row / pass
            {
                int q = tid & 31;          // ull index 0..31 within row
                int nl0 = tid >> 5;        // 0..7
                const ull* base = (kc == 0) ? A16 : X16;
                #pragma unroll
                for (int pass = 0; pass < 16; pass++) {
                    int nodeLoc = pass * 8 + nl0;
                    int node = tile * 128 + nodeLoc;
                    ull v = (node < n) ? base[(size_t)node * 32 + q] : 0ull;
                    *(ull*)(sS + nodeLoc * SSTRIDE + 2 * q) = v;
                }
            }
            __syncthreads();

            #pragma unroll
            for (int kstep = 0; kstep < 8; kstep++) {
                int p0 = kstep * 8;
                uint32_t bf[2][2];
                #pragma unroll
                for (int nt = 0; nt < 2; nt++) {
                    int wrow = (n0 + nt * 8 + g) * WSTRIDE + kc * 64 + p0 + t;
                    bf[nt][0] = sWhi[wrow];
                    bf[nt][1] = sWhi[wrow + 4];
                }
                uint32_t addr = aBase + (uint32_t)(p0 * 4);
                #pragma unroll
                for (int m = 0; m < 8; m++) {
                    uint32_t a0, a1, a2, a3;
                    LDSM_X4(a0, a1, a2, a3, addr);
                    addr += 16 * SSTRIDE * 4;
                    #pragma unroll
                    for (int nt = 0; nt < 2; nt++) {
                        MMA_F16(acc[m][nt], a0, a1, a2, a3, bf[nt][0], bf[nt][1]);
                    }
                }
            }
        }

        // epilogue: bias + relu; store fp16 (layer1) or fp32 (layer2).
        #pragma unroll
        for (int m = 0; m < 8; m++) {
            #pragma unroll
            for (int nt = 0; nt < 2; nt++) {
                int col = n0 + nt * 8 + 2 * t;
                float b0 = sBias[col], b1 = sBias[col + 1];
                int node0 = tile * 128 + m * 16 + g;
                int node1 = node0 + 8;
                float v00 = fmaxf(acc[m][nt][0] + b0, 0.f);
                float v01 = fmaxf(acc[m][nt][1] + b1, 0.f);
                float v10 = fmaxf(acc[m][nt][2] + b0, 0.f);
                float v11 = fmaxf(acc[m][nt][3] + b1, 0.f);
                if (outIsF16) {
                    __half* o16 = (__half*)outF16;
                    if (node0 < n) {
                        __half2 h = __float22half2_rn(make_float2(v00, v01));
                        *(__half2*)(o16 + (size_t)node0 * HID + col) = h;
                    }
                    if (node1 < n) {
                        __half2 h = __float22half2_rn(make_float2(v10, v11));
                        *(__half2*)(o16 + (size_t)node1 * HID + col) = h;
                    }
                } else {
                    if (node0 < n) {
                        float2 o; o.x = v00; o.y = v01;
                        *(float2*)(outF32 + (size_t)node0 * HID + col) = o;
                    }
                    if (node1 < n) {
                        float2 o; o.x = v10; o.y = v11;
                        *(float2*)(outF32 + (size_t)node1 * HID + col) = o;
                    }
                }
            }
        }
    }
}

// ---------------- logits head: warp per node ----------------
__global__ void logits_kernel(const float* __restrict__ h, const float* __restrict__ Wout,
                              const float* __restrict__ bout, float* __restrict__ out, int n) {
    int w = (blockIdx.x * blockDim.x + threadIdx.x) >> 5;
    int lane = threadIdx.x & 31;
    if (w >= n) return;
    float4 v = ((const float4*)(h + (size_t)w * HID))[lane];
    int k = lane * 4;
    float s0 = v.x * Wout[(k + 0) * 2 + 0] + v.y * Wout[(k + 1) * 2 + 0] +
               v.z * Wout[(k + 2) * 2 + 0] + v.w * Wout[(k + 3) * 2 + 0];
    float s1 = v.x * Wout[(k + 0) * 2 + 1] + v.y * Wout[(k + 1) * 2 + 1] +
               v.z * Wout[(k + 2) * 2 + 1] + v.w * Wout[(k + 3) * 2 + 1];
    #pragma unroll
    for (int off = 16; off > 0; off >>= 1) {
        s0 += __shfl_xor_sync(0xFFFFFFFFu, s0, off);
        s1 += __shfl_xor_sync(0xFFFFFFFFu, s1, off);
    }
    if (lane == 0) {
        out[(size_t)w * 2 + 0] = s0 + bout[0];
        out[(size_t)w * 2 + 1] = s1 + bout[1];
    }
}

// ---------------- launch ----------------
extern "C" void kernel_launch(void* const* d_in, const int* in_sizes, int n_in,
                              void* d_out, int out_size) {
    const float* x    = (const float*)d_in[0];
    const int*   ei   = (const int*)d_in[1];   // int32 on device
    const float* W1l  = (const float*)d_in[2];
    const float* W1r  = (const float*)d_in[3];
    const float* b1   = (const float*)d_in[4];
    const float* W2l  = (const float*)d_in[5];
    const float* W2r  = (const float*)d_in[6];
    const float* b2   = (const float*)d_in[7];
    const float* Wout = (const float*)d_in[8];
    const float* bout = (const float*)d_in[9];
    float* dout = (float*)d_out;

    int n = in_sizes[0] / HID;
    int E = in_sizes[1] / 2;
    const int* src = ei;
    const int* dst = ei + E;

    int *p_counts, *p_off, *p_cursor, *p_esrc;
    ull *p_x16, *p_h16, *p_aggr16;
    float *p_h2;
    uint4 *p_whi;
    cudaGetSymbolAddress((void**)&p_counts, g_counts);
    cudaGetSymbolAddress((void**)&p_off,    g_off);
    cudaGetSymbolAddress((void**)&p_cursor, g_cursor);
    cudaGetSymbolAddress((void**)&p_esrc,   g_esrc);
    cudaGetSymbolAddress((void**)&p_x16,    g_x16);
    cudaGetSymbolAddress((void**)&p_h16,    g_h16);
    cudaGetSymbolAddress((void**)&p_aggr16, g_aggr16);
    cudaGetSymbolAddress((void**)&p_h2,     g_h2);
    cudaGetSymbolAddress((void**)&p_whi,    g_whi);

    cudaFuncSetAttribute(layer_kernel, cudaFuncAttributeMaxDynamicSharedMemorySize, LAYER_SMEM);

    // tuple output: logits [n*2] then h [n*128]
    float* hOut = ((size_t)out_size >= (size_t)n * (HID + 2)) ? (dout + (size_t)n * 2) : p_h2;

    int total4 = n * HID / 4;
    int grid1 = (max(E, total4) + 255) / 256;

    // ---- launches 1-4 (layer1 is launch #6 -> profiled by ncu -s 5 -c 1) ----
    hist_xcvt_kernel<<<grid1, 256>>>(dst, p_counts, E, x, p_x16, total4);
    scan_kernel<<<1, 1024>>>(p_counts, p_off, p_cursor, n);
    fill_kernel<<<(E + 255) / 256, 256>>>(src, dst, p_cursor, p_esrc, E);
    wsplit_kernel<<<256, 256>>>(W1l, W1r, W2l, W2r);

    int gatherGrid = (n * 32 + 255) / 256;
    int nTiles = (n + 127) >> 7;
    int layerGrid = nTiles < 296 ? nTiles : 296;

    // ---- layer 1 (h1 stored fp16) ----
    gather_kernel<<<gatherGrid, 256>>>(p_x16, p_esrc, p_off, p_aggr16, n);
    layer_kernel<<<layerGrid, 256, LAYER_SMEM>>>(p_aggr16, p_x16, p_whi, b1,
                                                 nullptr, p_h16, n, 1);

    // ---- layer 2 (h stored fp32 to output) ----
    gather_kernel<<<gatherGrid, 256>>>(p_h16, p_esrc, p_off, p_aggr16, n);
    layer_kernel<<<layerGrid, 256, LAYER_SMEM>>>(p_aggr16, p_h16, p_whi + 4224, b2,
                                                 hOut, nullptr, n, 0);

    // ---- head ----
    logits_kernel<<<(n * 32 + 255) / 256, 256>>>(hOut, Wout, bout, dout, n);
}

// round 16
// speedup vs baseline: 1.0890x; 1.0890x over previous
#include <cuda_runtime.h>
#include <cuda_bf16.h>
#include <cuda_fp16.h>
#include <cstdint>
#include <math.h>

#define HID 128
#define MAXN 50000
#define MAXE 800000

typedef unsigned long long ull;

// ---------------- scratch (device globals; zero-initialized at load) ----------------
__device__ int   g_counts[MAXN + 1];   // scan_kernel re-zeroes after use each call
__device__ int   g_off[MAXN + 1];
__device__ int   g_cursor[MAXN];
__device__ int   g_esrc[MAXE];
__device__ ull   g_x16[(size_t)MAXN * 32];    // x as fp16 rows (128 halves = 32 ull)
__device__ ull   g_h16[(size_t)MAXN * 32];    // h1 as fp16 rows
__device__ ull   g_aggr16[(size_t)MAXN * 32]; // mean-aggregated features, fp16
__device__ float g_h2[(size_t)MAXN * HID];    // fallback h buffer (fp32)
// W fp16, pre-laid-out as [col][264 halves] (word stride 132), per layer
__device__ uint4 g_whi[2][4224];   // 2 x 67584 B

#define MMA_F16(c, a0, a1, a2, a3, b0, b1) \
    asm volatile("mma.sync.aligned.m16n8k16.row.col.f32.f16.f16.f32 " \
        "{%0,%1,%2,%3}, {%4,%5,%6,%7}, {%8,%9}, {%0,%1,%2,%3};" \
        : "+f"((c)[0]), "+f"((c)[1]), "+f"((c)[2]), "+f"((c)[3]) \
        : "r"(a0), "r"(a1), "r"(a2), "r"(a3), "r"(b0), "r"(b1))

// ---------------- launch 1: edge histogram + x->fp16 + W->fp16 (fused, independent) ------------
__global__ void hist_xcvt_wsplit_kernel(
        const int* __restrict__ dst, int* __restrict__ counts, int E,
        const float* __restrict__ x, ull* __restrict__ x16, int total4,
        const float* __restrict__ W1l, const float* __restrict__ W1r,
        const float* __restrict__ W2l, const float* __restrict__ W2r) {
    int i = blockIdx.x * blockDim.x + threadIdx.x;
    if (i < E) atomicAdd(&counts[dst[i]], 1);
    if (i < total4) {
        float4 v = ((const float4*)x)[i];
        __half2 h0 = __float22half2_rn(make_float2(v.x, v.y));
        __half2 h1 = __float22half2_rn(make_float2(v.z, v.w));
        x16[i] = (ull)(*(uint32_t*)&h0) | ((ull)(*(uint32_t*)&h1) << 32);
    }
    if (i < 2 * 256 * 128) {
        int layer = i >> 15;
        int r = i & 32767;
        int k = r >> 7;
        int col = r & 127;
        const float* srcm;
        if (layer == 0) srcm = (k < 128) ? (W1l + (size_t)k * 128) : (W1r + (size_t)(k - 128) * 128);
        else            srcm = (k < 128) ? (W2l + (size_t)k * 128) : (W2r + (size_t)(k - 128) * 128);
        float w = srcm[col];
        __half h = __float2half(w);
        ((uint16_t*)g_whi[layer])[col * 264 + k] = *(uint16_t*)&h;
    }
}

// ---------------- launch 2: single-block scan ----------------
__global__ void scan_kernel(int* __restrict__ counts, int* __restrict__ off,
                            int* __restrict__ cursor, int n) {
    __shared__ int part[1024];
    int tid = threadIdx.x;
    int chunk = (n + 1023) >> 10;
    int start = tid * chunk;
    int end = start + chunk; if (end > n) end = n;
    int s = 0;
    #pragma unroll 4
    for (int i = start; i < end; i++) s += counts[i];
    part[tid] = s;
    __syncthreads();
    for (int d = 1; d < 1024; d <<= 1) {
        int v = (tid >= d) ? part[tid - d] : 0;
        __syncthreads();
        part[tid] += v;
        __syncthreads();
    }
    int pre = (tid == 0) ? 0 : part[tid - 1];
    for (int i = start; i < end; i++) {
        int c = counts[i];
        counts[i] = 0;          // leave zeroed for next call's hist
        off[i] = pre;
        cursor[i] = pre;
        pre += c;
    }
    if (end == n) off[n] = pre;
}

// ---------------- launch 3: CSR fill ----------------
__global__ void fill_kernel(const int* __restrict__ src, const int* __restrict__ dst,
                            int* __restrict__ cursor, int* __restrict__ esrc, int E) {
    int e = blockIdx.x * blockDim.x + threadIdx.x;
    if (e < E) {
        int d = dst[e];
        int pos = atomicAdd(&cursor[d], 1);
        esrc[pos] = src[e];
    }
}

// ---------------- gather-aggregate (mean) over fp16 rows: warp per dst node, MLP=8 ----------------
__global__ void gather_kernel(const ull* __restrict__ feat16, const int* __restrict__ esrc,
                              const int* __restrict__ off, ull* __restrict__ aggr16, int n) {
    int w = (blockIdx.x * blockDim.x + threadIdx.x) >> 5;
    int lane = threadIdx.x & 31;
    if (w >= n) return;
    int o0 = off[w], o1 = off[w + 1];
    float a0 = 0.f, a1 = 0.f, a2 = 0.f, a3 = 0.f;
    int k = o0;
    for (; k + 8 <= o1; k += 8) {
        ull vv[8];
        #pragma unroll
        for (int e = 0; e < 8; e++) {
            int s = __ldg(esrc + k + e);
            vv[e] = feat16[(size_t)s * 32 + lane];
        }
        #pragma unroll
        for (int e = 0; e < 8; e++) {
            uint32_t lo = (uint32_t)vv[e], hi = (uint32_t)(vv[e] >> 32);
            float2 f0 = __half22float2(*(__half2*)&lo);
            float2 f1 = __half22float2(*(__half2*)&hi);
            a0 += f0.x; a1 += f0.y; a2 += f1.x; a3 += f1.y;
        }
    }
    for (; k < o1; k++) {
        int s = __ldg(esrc + k);
        ull v = feat16[(size_t)s * 32 + lane];
        uint32_t lo = (uint32_t)v, hi = (uint32_t)(v >> 32);
        float2 f0 = __half22float2(*(__half2*)&lo);
        float2 f1 = __half22float2(*(__half2*)&hi);
        a0 += f0.x; a1 += f0.y; a2 += f1.x; a3 += f1.y;
    }
    float inv = 1.0f / fmaxf((float)(o1 - o0), 1.0f);
    __half2 r0 = __float22half2_rn(make_float2(a0 * inv, a1 * inv));
    __half2 r1 = __float22half2_rn(make_float2(a2 * inv, a3 * inv));
    aggr16[(size_t)w * 32 + lane] = (ull)(*(uint32_t*)&r0) | ((ull)(*(uint32_t*)&r1) << 32);
}

// ---------------- HMMA (mma.sync fp16) SAGE layer, 2 CTAs/SM, optional fused logits ----------------
// out[i][j] = relu( b[j] + sum_{k<256} S[i][k] W[k][j] ), S=[A|X] (fp16), W=[Wl;Wr] (fp16).
// If doLogits: h-tile is also stashed (fp16) in sS after the MMAs; 128 threads then
// dot their node's row with smem-staged Wout and write logits.
#define WSTRIDE 132
#define SSTRIDE 68
#define SM_BIAS 0
#define SM_WOUT 512
#define SM_WHI  2048
#define SM_S    (2048 + 128 * WSTRIDE * 4)
#define LAYER_SMEM (SM_S + 128 * SSTRIDE * 4)

__global__ void __launch_bounds__(256, 2)
layer_kernel(const ull* __restrict__ A16, const ull* __restrict__ X16,
             const uint4* __restrict__ whi, const float* __restrict__ bias,
             float* __restrict__ outF32, ull* __restrict__ outF16,
             int n, int outIsF16,
             const float* __restrict__ Wout, const float* __restrict__ bout,
             float* __restrict__ logits, int doLogits) {
    extern __shared__ char smem[];
    float* sBias = (float*)(smem + SM_BIAS);
    float* sWout = (float*)(smem + SM_WOUT);   // [128][2]
    uint32_t* sWhi = (uint32_t*)(smem + SM_WHI);
    uint32_t* sS   = (uint32_t*)(smem + SM_S);

    int tid = threadIdx.x;
    int wid = tid >> 5;
    int lane = tid & 31;
    int g = lane >> 2;
    int t = lane & 3;
    int n0 = wid * 16;

    // ---- stage W: pure linear copy (4224 uint4); bias; Wout ----
    {
        uint4* dh = (uint4*)sWhi;
        for (int i = tid; i < 4224; i += 256) dh[i] = whi[i];
        if (tid < 128) sBias[tid] = bias[tid];
        if (doLogits && tid < 256) sWout[tid] = Wout[tid];
    }
    float bo0 = 0.f, bo1 = 0.f;
    if (doLogits) { bo0 = __ldg(bout); bo1 = __ldg(bout + 1); }

    int nTiles = (n + 127) >> 7;
    for (int tile = blockIdx.x; tile < nTiles; tile += gridDim.x) {
        float acc[8][2][4];
        #pragma unroll
        for (int m = 0; m < 8; m++)
            #pragma unroll
            for (int nt = 0; nt < 2; nt++)
                #pragma unroll
                for (int q = 0; q < 4; q++) acc[m][nt][q] = 0.f;

        #pragma unroll
        for (int kc = 0; kc < 2; kc++) {
            __syncthreads();   // protects sS reuse (and sW staging on first pass)
            // stage S chunk (128 nodes x 128 k): pure 8B copy, warp = 1 node row / pass
            {
                int q = tid & 31;          // ull index 0..31 within row
                int nl0 = tid >> 5;        // 0..7
                const ull* base = (kc == 0) ? A16 : X16;
                #pragma unroll
                for (int pass = 0; pass < 16; pass++) {
                    int nodeLoc = pass * 8 + nl0;
                    int node = tile * 128 + nodeLoc;
                    ull v = (node < n) ? base[(size_t)node * 32 + q] : 0ull;
                    *(ull*)(sS + nodeLoc * SSTRIDE + 2 * q) = v;
                }
            }
            __syncthreads();

            #pragma unroll
            for (int kstep = 0; kstep < 8; kstep++) {
                int p0 = kstep * 8;
                uint32_t bf[2][2];
                #pragma unroll
                for (int nt = 0; nt < 2; nt++) {
                    int wrow = (n0 + nt * 8 + g) * WSTRIDE + kc * 64 + p0 + t;
                    bf[nt][0] = sWhi[wrow];
                    bf[nt][1] = sWhi[wrow + 4];
                }
                #pragma unroll
                for (int m = 0; m < 8; m++) {
                    int r0 = (m * 16 + g) * SSTRIDE + p0 + t;
                    int r1 = r0 + 8 * SSTRIDE;
                    uint32_t a0 = sS[r0], a1 = sS[r1];
                    uint32_t a2 = sS[r0 + 4], a3 = sS[r1 + 4];
                    #pragma unroll
                    for (int nt = 0; nt < 2; nt++) {
                        MMA_F16(acc[m][nt], a0, a1, a2, a3, bf[nt][0], bf[nt][1]);
                    }
                }
            }
        }

        if (doLogits) __syncthreads();   // all MMA reads of sS done before h-stash overwrites it

        // epilogue: bias + relu; store h (fp16 or fp32); optionally stash fp16 h-tile in sS
        #pragma unroll
        for (int m = 0; m < 8; m++) {
            #pragma unroll
            for (int nt = 0; nt < 2; nt++) {
                int col = n0 + nt * 8 + 2 * t;
                float b0 = sBias[col], b1 = sBias[col + 1];
                int nodeLoc0 = m * 16 + g;
                int nodeLoc1 = nodeLoc0 + 8;
                int node0 = tile * 128 + nodeLoc0;
                int node1 = tile * 128 + nodeLoc1;
                float v00 = fmaxf(acc[m][nt][0] + b0, 0.f);
                float v01 = fmaxf(acc[m][nt][1] + b1, 0.f);
                float v10 = fmaxf(acc[m][nt][2] + b0, 0.f);
                float v11 = fmaxf(acc[m][nt][3] + b1, 0.f);
                __half2 h2a = __float22half2_rn(make_float2(v00, v01));
                __half2 h2b = __float22half2_rn(make_float2(v10, v11));
                if (doLogits) {
                    sS[nodeLoc0 * SSTRIDE + (col >> 1)] = *(uint32_t*)&h2a;
                    sS[nodeLoc1 * SSTRIDE + (col >> 1)] = *(uint32_t*)&h2b;
                }
                if (outIsF16) {
                    __half* o16 = (__half*)outF16;
                    if (node0 < n) *(__half2*)(o16 + (size_t)node0 * HID + col) = h2a;
                    if (node1 < n) *(__half2*)(o16 + (size_t)node1 * HID + col) = h2b;
                } else {
                    if (node0 < n) {
                        float2 o; o.x = v00; o.y = v01;
                        *(float2*)(outF32 + (size_t)node0 * HID + col) = o;
                    }
                    if (node1 < n) {
                        float2 o; o.x = v10; o.y = v11;
                        *(float2*)(outF32 + (size_t)node1 * HID + col) = o;
                    }
                }
            }
        }

        if (doLogits) {
            __syncthreads();
            if (tid < 128) {
                int node = tile * 128 + tid;
                if (node < n) {
                    const uint32_t* row = sS + tid * SSTRIDE;
                    float pl0 = bo0, pl1 = bo1;
                    #pragma unroll 16
                    for (int wq = 0; wq < 64; wq++) {
                        uint32_t p = row[wq];
                        float2 f = __half22float2(*(__half2*)&p);
                        pl0 = fmaf(f.x, sWout[(2 * wq) * 2 + 0], pl0);
                        pl1 = fmaf(f.x, sWout[(2 * wq) * 2 + 1], pl1);
                        pl0 = fmaf(f.y, sWout[(2 * wq + 1) * 2 + 0], pl0);
                        pl1 = fmaf(f.y, sWout[(2 * wq + 1) * 2 + 1], pl1);
                    }
                    float2 o; o.x = pl0; o.y = pl1;
                    *(float2*)(logits + (size_t)node * 2) = o;
                }
            }
        }
    }
}

// ---------------- launch ----------------
extern "C" void kernel_launch(void* const* d_in, const int* in_sizes, int n_in,
                              void* d_out, int out_size) {
    const float* x    = (const float*)d_in[0];
    const int*   ei   = (const int*)d_in[1];   // int32 on device
    const float* W1l  = (const float*)d_in[2];
    const float* W1r  = (const float*)d_in[3];
    const float* b1   = (const float*)d_in[4];
    const float* W2l  = (const float*)d_in[5];
    const float* W2r  = (const float*)d_in[6];
    const float* b2   = (const float*)d_in[7];
    const float* Wout = (const float*)d_in[8];
    const float* bout = (const float*)d_in[9];
    float* dout = (float*)d_out;

    int n = in_sizes[0] / HID;
    int E = in_sizes[1] / 2;
    const int* src = ei;
    const int* dst = ei + E;

    int *p_counts, *p_off, *p_cursor, *p_esrc;
    ull *p_x16, *p_h16, *p_aggr16;
    float *p_h2;
    uint4 *p_whi;
    cudaGetSymbolAddress((void**)&p_counts, g_counts);
    cudaGetSymbolAddress((void**)&p_off,    g_off);
    cudaGetSymbolAddress((void**)&p_cursor, g_cursor);
    cudaGetSymbolAddress((void**)&p_esrc,   g_esrc);
    cudaGetSymbolAddress((void**)&p_x16,    g_x16);
    cudaGetSymbolAddress((void**)&p_h16,    g_h16);
    cudaGetSymbolAddress((void**)&p_aggr16, g_aggr16);
    cudaGetSymbolAddress((void**)&p_h2,     g_h2);
    cudaGetSymbolAddress((void**)&p_whi,    g_whi);

    cudaFuncSetAttribute(layer_kernel, cudaFuncAttributeMaxDynamicSharedMemorySize, LAYER_SMEM);

    // tuple output: logits [n*2] then h [n*128]
    float* hOut = ((size_t)out_size >= (size_t)n * (HID + 2)) ? (dout + (size_t)n * 2) : p_h2;

    int total4 = n * HID / 4;
    int grid1 = (max(E, total4) + 255) / 256;

    // ---- launches 1-3: CSR build + converts ----
    hist_xcvt_wsplit_kernel<<<grid1, 256>>>(dst, p_counts, E, x, p_x16, total4,
                                            W1l, W1r, W2l, W2r);
    scan_kernel<<<1, 1024>>>(p_counts, p_off, p_cursor, n);
    fill_kernel<<<(E + 255) / 256, 256>>>(src, dst, p_cursor, p_esrc, E);

    int gatherGrid = (n * 32 + 255) / 256;
    int nTiles = (n + 127) >> 7;
    int layerGrid = nTiles < 296 ? nTiles : 296;

    // ---- layer 1 (h1 stored fp16) ----
    gather_kernel<<<gatherGrid, 256>>>(p_x16, p_esrc, p_off, p_aggr16, n);
    layer_kernel<<<layerGrid, 256, LAYER_SMEM>>>(p_aggr16, p_x16, p_whi, b1,
                                                 nullptr, p_h16, n, 1,
                                                 Wout, bout, dout, 0);

    // ---- layer 2 (h stored fp32 to output; fused logits head) ----
    gather_kernel<<<gatherGrid, 256>>>(p_h16, p_esrc, p_off, p_aggr16, n);
    layer_kernel<<<layerGrid, 256, LAYER_SMEM>>>(p_aggr16, p_h16, p_whi + 4224, b2,
                                                 hOut, nullptr, n, 0,
                                                 Wout, bout, dout, 1);
}